// round 2
// baseline (speedup 1.0000x reference)
#include <cuda_runtime.h>
#include <cuda_fp16.h>

// ---------------------------------------------------------------------------
// Tri-plane sampling, channel-last fp16 scratch:
//   phase 1: one fused kernel transposes all 9 grids [32,R,R] -> [R*R,32] fp16
//            (66 MB scratch -> fully L2-resident on GB300's 126 MB L2)
//   phase 2: warp-per-point sampling, lane = channel; every corner gather is
//            one 64B coalesced transaction, output store is 128B coalesced.
// ---------------------------------------------------------------------------

#define TOTAL_PX 1032192u   // 3*128^2 + 3*256^2 + 3*512^2
__device__ __half g_tp[TOTAL_PX * 32];  // 66 MB fp16 scratch

__constant__ unsigned c_base_px[9] = {0u,      16384u,  32768u,
                                      49152u,  114688u, 180224u,
                                      245760u, 507904u, 770048u};
__constant__ int      c_npix[9]    = {16384, 16384, 16384,
                                      65536, 65536, 65536,
                                      262144, 262144, 262144};
// tile_start[i] = base_px[i] / 32  (32 pixels per block)
__constant__ int      c_tile_start[9] = {0, 512, 1024,
                                         1536, 3584, 5632,
                                         7680, 15872, 24064};
#define TOTAL_TILES 32256   // TOTAL_PX / 32

struct GridPtrs { const float* g[9]; };

__global__ void __launch_bounds__(256)
transpose_all(GridPtrs ptrs) {
    __shared__ float tile[32][33];
    const int b = blockIdx.x;

    // which grid does this tile belong to?
    int gi = 0;
    #pragma unroll
    for (int i = 1; i < 9; i++)
        if (b >= c_tile_start[i]) gi = i;

    const float* __restrict__ g = ptrs.g[gi];
    const int npix = c_npix[gi];
    const int pix0 = (b - c_tile_start[gi]) * 32;

    const int tx = threadIdx.x;   // 0..31
    const int ty = threadIdx.y;   // 0..7

    #pragma unroll
    for (int c = ty; c < 32; c += 8) {
        // coalesced read along pixel dim for channel c
        tile[tx][c] = __ldg(g + (size_t)c * npix + pix0 + tx);
    }
    __syncthreads();

    __half* dst = g_tp + ((size_t)c_base_px[gi] + pix0) * 32;
    #pragma unroll
    for (int r = ty; r < 32; r += 8) {
        // coalesced 64B write: 32 consecutive fp16 channels of pixel (pix0+r)
        dst[(size_t)r * 32 + tx] = __float2half_rn(tile[r][tx]);
    }
}

__global__ void __launch_bounds__(256)
sample_kernel(const float* __restrict__ pts, float* __restrict__ out, int n) {
    const int gw   = (int)((blockIdx.x * (unsigned)blockDim.x + threadIdx.x) >> 5);
    const int lane = threadIdx.x & 31;
    if (gw >= n) return;

    // broadcast loads (all lanes same address -> 1 transaction each)
    const float vx = __ldg(pts + 3 * (size_t)gw + 0);
    const float vy = __ldg(pts + 3 * (size_t)gw + 1);
    const float vz = __ldg(pts + 3 * (size_t)gw + 2);

    // p = (v - BOUNDS) * (2 / (-2*BOUNDS)) - 1, BOUNDS = 1.6
    const float px = (vx - 1.6f) * (-0.625f) - 1.0f;
    const float py = (vy - 1.6f) * (-0.625f) - 1.0f;
    const float pz = (vz - 1.6f) * (-0.625f) - 1.0f;

    // plane -> (W coord, H coord)
    const float cw[3] = {py, px, px};
    const float ch[3] = {pz, pz, py};

    const int Rs[3] = {128, 256, 512};
    const unsigned base_px[9] = {0u,      16384u,  32768u,
                                 49152u,  114688u, 180224u,
                                 245760u, 507904u, 770048u};

    float* outp = out + (size_t)gw * 288 + lane;

    #pragma unroll
    for (int l = 0; l < 3; l++) {
        const int   R   = Rs[l];
        const float Rm1 = (float)(R - 1);
        #pragma unroll
        for (int p = 0; p < 3; p++) {
            // match reference op order: ((c + 1) * 0.5) * (W-1), then clip
            float x = (cw[p] + 1.0f) * 0.5f * Rm1;
            x = fminf(fmaxf(x, 0.0f), Rm1);
            float y = (ch[p] + 1.0f) * 0.5f * Rm1;
            y = fminf(fmaxf(y, 0.0f), Rm1);

            const float x0f = floorf(x), y0f = floorf(y);
            const float wx = x - x0f,    wy = y - y0f;
            const int x0 = (int)x0f,     y0 = (int)y0f;
            const int x1 = min(x0 + 1, R - 1);
            const int y1 = min(y0 + 1, R - 1);

            const __half* base = g_tp + (size_t)base_px[l * 3 + p] * 32;
            // each load: 32 lanes x 2B consecutive = one 64B transaction
            const float v00 = __half2float(__ldg(base + (((size_t)y0 * R + x0) << 5) + lane));
            const float v01 = __half2float(__ldg(base + (((size_t)y0 * R + x1) << 5) + lane));
            const float v10 = __half2float(__ldg(base + (((size_t)y1 * R + x0) << 5) + lane));
            const float v11 = __half2float(__ldg(base + (((size_t)y1 * R + x1) << 5) + lane));

            const float r = (v00 * (1.0f - wx) + v01 * wx) * (1.0f - wy)
                          + (v10 * (1.0f - wx) + v11 * wx) * wy;

            outp[(l * 3 + p) * 32] = r;  // coalesced 128B store
        }
    }
}

extern "C" void kernel_launch(void* const* d_in, const int* in_sizes, int n_in,
                              void* d_out, int out_size) {
    const float* pts = (const float*)d_in[0];
    const int n = in_sizes[0] / 3;  // 300000 points

    GridPtrs ptrs;
    for (int i = 0; i < 9; i++) ptrs.g[i] = (const float*)d_in[1 + i];

    // 1) fused transpose+fp16-convert of all 9 grids (one launch)
    dim3 tthreads(32, 8);
    transpose_all<<<TOTAL_TILES, tthreads>>>(ptrs);

    // 2) warp-per-point sampling (8 warps / 256-thread block)
    const int blocks = (n + 7) / 8;
    sample_kernel<<<blocks, 256>>>(pts, (float*)d_out, n);
}

// round 3
// speedup vs baseline: 1.6731x; 1.6731x over previous
#include <cuda_runtime.h>
#include <cuda_fp16.h>

// ---------------------------------------------------------------------------
// Tri-plane sampling, channel-last fp16 scratch:
//   phase 1: fused transpose of 9 grids [32,R,R] -> [R*R,32] fp16 (66 MB,
//            L2-resident). 128-px tiles, conflict-free smem, 128B writes.
//   phase 2: 2 points per warp, lane = channel PAIR (__half2): halves the
//            per-point instruction count vs lane-per-channel.
// ---------------------------------------------------------------------------

#define TOTAL_PX 1032192u   // 3*128^2 + 3*256^2 + 3*512^2
__device__ __half g_tp[TOTAL_PX * 32];  // 66 MB fp16 scratch

__constant__ unsigned c_base_px[9] = {0u,      16384u,  32768u,
                                      49152u,  114688u, 180224u,
                                      245760u, 507904u, 770048u};
__constant__ int      c_npix[9]    = {16384, 16384, 16384,
                                      65536, 65536, 65536,
                                      262144, 262144, 262144};
// tile_start[i] = base_px[i] / 128  (128 pixels per block)
__constant__ int      c_tile_start[9] = {0, 128, 256,
                                         384, 896, 1408,
                                         1920, 3968, 6016};
#define TOTAL_TILES 8064    // TOTAL_PX / 128

struct GridPtrs { const float* g[9]; };

__global__ void __launch_bounds__(256)
transpose_all(GridPtrs ptrs) {
    __shared__ float tile[128][33];   // stride 33: conflict-free both phases
    const int b = blockIdx.x;

    int gi = 0;
    #pragma unroll
    for (int i = 1; i < 9; i++)
        if (b >= c_tile_start[i]) gi = i;

    const float* __restrict__ g = ptrs.g[gi];
    const int npix = c_npix[gi];
    const int pix0 = (b - c_tile_start[gi]) * 128;

    const int tx = threadIdx.x & 31;
    const int ty = threadIdx.x >> 5;   // warp id 0..7

    // load: channel-major, 128B coalesced rows; smem bank = (px + c) -> free
    #pragma unroll
    for (int c = ty; c < 32; c += 8) {
        const float* row = g + (size_t)c * npix + pix0;
        #pragma unroll
        for (int j = 0; j < 4; j++)
            tile[32 * j + tx][c] = __ldg(row + 32 * j + tx);
    }
    __syncthreads();

    // store: each warp owns 16 pixels, writes 2 pixels/step as half2
    // -> 32 lanes x 4B = 128B contiguous per step
    __half2* dst = (__half2*)g_tp + ((size_t)c_base_px[gi] + pix0) * 16;
    const int hl = tx & 15;
    #pragma unroll
    for (int s = 0; s < 8; s++) {
        const int pix = ty * 16 + s * 2 + (tx >> 4);
        const float a = tile[pix][2 * hl];
        const float c2 = tile[pix][2 * hl + 1];
        dst[(size_t)pix * 16 + hl] = __floats2half2_rn(a, c2);
    }
}

__global__ void __launch_bounds__(256)
sample_kernel(const float* __restrict__ pts, float* __restrict__ out, int n) {
    const int warp = (int)((blockIdx.x * 256u + threadIdx.x) >> 5);
    const int lane = threadIdx.x & 31;
    const int hl   = lane & 15;           // channel-pair index 0..15
    const int pt   = warp * 2 + (lane >> 4);
    if (pt >= n) return;

    const float vx = __ldg(pts + 3 * (size_t)pt + 0);
    const float vy = __ldg(pts + 3 * (size_t)pt + 1);
    const float vz = __ldg(pts + 3 * (size_t)pt + 2);

    // p = (v - 1.6) * (-0.625) - 1
    const float px = (vx - 1.6f) * (-0.625f) - 1.0f;
    const float py = (vy - 1.6f) * (-0.625f) - 1.0f;
    const float pz = (vz - 1.6f) * (-0.625f) - 1.0f;

    const float cw[3] = {py, px, px};   // plane -> W coord
    const float ch[3] = {pz, pz, py};   // plane -> H coord

    const int Rs[3] = {128, 256, 512};
    const unsigned base_px[9] = {0u,      16384u,  32768u,
                                 49152u,  114688u, 180224u,
                                 245760u, 507904u, 770048u};

    const __half2* __restrict__ gp = (const __half2*)g_tp;
    float2* outp = (float2*)(out + (size_t)pt * 288) + hl;

    #pragma unroll
    for (int l = 0; l < 3; l++) {
        const int   R   = Rs[l];
        const float Rm1 = (float)(R - 1);
        #pragma unroll
        for (int p = 0; p < 3; p++) {
            float x = (cw[p] + 1.0f) * 0.5f * Rm1;
            x = fminf(fmaxf(x, 0.0f), Rm1);
            float y = (ch[p] + 1.0f) * 0.5f * Rm1;
            y = fminf(fmaxf(y, 0.0f), Rm1);

            const float x0f = floorf(x), y0f = floorf(y);
            const float wx = x - x0f,    wy = y - y0f;
            const int x0 = (int)x0f,     y0 = (int)y0f;
            const int x1 = min(x0 + 1, R - 1);
            const int y1 = min(y0 + 1, R - 1);

            const __half2* base = gp + (size_t)base_px[l * 3 + p] * 16;
            const float2 f00 = __half22float2(__ldg(base + (((size_t)y0 * R + x0) << 4) + hl));
            const float2 f01 = __half22float2(__ldg(base + (((size_t)y0 * R + x1) << 4) + hl));
            const float2 f10 = __half22float2(__ldg(base + (((size_t)y1 * R + x0) << 4) + hl));
            const float2 f11 = __half22float2(__ldg(base + (((size_t)y1 * R + x1) << 4) + hl));

            const float iwx = 1.0f - wx, iwy = 1.0f - wy;
            float2 r;
            r.x = (f00.x * iwx + f01.x * wx) * iwy + (f10.x * iwx + f11.x * wx) * wy;
            r.y = (f00.y * iwx + f01.y * wx) * iwy + (f10.y * iwx + f11.y * wx) * wy;

            outp[(l * 3 + p) * 16] = r;   // 128B coalesced per half-warp pair
        }
    }
}

extern "C" void kernel_launch(void* const* d_in, const int* in_sizes, int n_in,
                              void* d_out, int out_size) {
    const float* pts = (const float*)d_in[0];
    const int n = in_sizes[0] / 3;  // 300000 points

    GridPtrs ptrs;
    for (int i = 0; i < 9; i++) ptrs.g[i] = (const float*)d_in[1 + i];

    transpose_all<<<TOTAL_TILES, 256>>>(ptrs);

    // 2 points per warp, 8 warps per block -> 16 points per block
    const int blocks = (n + 15) / 16;
    sample_kernel<<<blocks, 256>>>(pts, (float*)d_out, n);
}

// round 4
// speedup vs baseline: 1.7814x; 1.0647x over previous
#include <cuda_runtime.h>
#include <cuda_fp16.h>

// ---------------------------------------------------------------------------
// Tri-plane sampling, channel-last fp16 scratch:
//   phase 1: fused transpose of 9 grids [32,R,R] -> [R*R,32] fp16 (66 MB,
//            L2-resident). At HBM roofline (~7.7 TB/s), unchanged from R3.
//   phase 2: 8 points per warp, 4 lanes per point, each lane loads a 16B
//            uint4 (8 fp16 channels) per corner -> 4x fewer gather/addr
//            instructions per point than R3. fp32 lerp for precision.
// ---------------------------------------------------------------------------

#define TOTAL_PX 1032192u   // 3*128^2 + 3*256^2 + 3*512^2
__device__ __half g_tp[TOTAL_PX * 32];  // 66 MB fp16 scratch

__constant__ unsigned c_base_px[9] = {0u,      16384u,  32768u,
                                      49152u,  114688u, 180224u,
                                      245760u, 507904u, 770048u};
__constant__ int      c_npix[9]    = {16384, 16384, 16384,
                                      65536, 65536, 65536,
                                      262144, 262144, 262144};
__constant__ int      c_tile_start[9] = {0, 128, 256,
                                         384, 896, 1408,
                                         1920, 3968, 6016};
#define TOTAL_TILES 8064    // TOTAL_PX / 128

struct GridPtrs { const float* g[9]; };

__global__ void __launch_bounds__(256)
transpose_all(GridPtrs ptrs) {
    __shared__ float tile[128][33];   // stride 33: conflict-free both phases
    const int b = blockIdx.x;

    int gi = 0;
    #pragma unroll
    for (int i = 1; i < 9; i++)
        if (b >= c_tile_start[i]) gi = i;

    const float* __restrict__ g = ptrs.g[gi];
    const int npix = c_npix[gi];
    const int pix0 = (b - c_tile_start[gi]) * 128;

    const int tx = threadIdx.x & 31;
    const int ty = threadIdx.x >> 5;   // warp id 0..7

    #pragma unroll
    for (int c = ty; c < 32; c += 8) {
        const float* row = g + (size_t)c * npix + pix0;
        #pragma unroll
        for (int j = 0; j < 4; j++)
            tile[32 * j + tx][c] = __ldg(row + 32 * j + tx);
    }
    __syncthreads();

    __half2* dst = (__half2*)g_tp + ((size_t)c_base_px[gi] + pix0) * 16;
    const int hl = tx & 15;
    #pragma unroll
    for (int s = 0; s < 8; s++) {
        const int pix = ty * 16 + s * 2 + (tx >> 4);
        const float a = tile[pix][2 * hl];
        const float c2 = tile[pix][2 * hl + 1];
        dst[(size_t)pix * 16 + hl] = __floats2half2_rn(a, c2);
    }
}

// lerp 8 channels held in a uint4-of-half2
__device__ __forceinline__ void lerp8(const uint4& u00, const uint4& u01,
                                      const uint4& u10, const uint4& u11,
                                      float wx, float wy,
                                      float4& r0, float4& r1) {
    const float iwx = 1.0f - wx, iwy = 1.0f - wy;
    #pragma unroll
    for (int k = 0; k < 4; k++) {
        const unsigned a = (&u00.x)[k], b = (&u01.x)[k];
        const unsigned c = (&u10.x)[k], d = (&u11.x)[k];
        const float2 fa = __half22float2(*(const __half2*)&a);
        const float2 fb = __half22float2(*(const __half2*)&b);
        const float2 fc = __half22float2(*(const __half2*)&c);
        const float2 fd = __half22float2(*(const __half2*)&d);
        float rx = (fa.x * iwx + fb.x * wx) * iwy + (fc.x * iwx + fd.x * wx) * wy;
        float ry = (fa.y * iwx + fb.y * wx) * iwy + (fc.y * iwx + fd.y * wx) * wy;
        float* dst = (k < 2) ? &r0.x : &r1.x;
        dst[(k & 1) * 2 + 0] = rx;
        dst[(k & 1) * 2 + 1] = ry;
    }
}

__global__ void __launch_bounds__(256)
sample_kernel(const float* __restrict__ pts, float* __restrict__ out, int n) {
    const int warp = (int)((blockIdx.x * 256u + threadIdx.x) >> 5);
    const int lane = threadIdx.x & 31;
    const int q    = lane & 3;           // 16B chunk index: channels [8q, 8q+8)
    const int pt   = warp * 8 + (lane >> 2);
    if (pt >= n) return;

    const float vx = __ldg(pts + 3 * (size_t)pt + 0);
    const float vy = __ldg(pts + 3 * (size_t)pt + 1);
    const float vz = __ldg(pts + 3 * (size_t)pt + 2);

    // p = (v - 1.6) * (-0.625) - 1
    const float px = (vx - 1.6f) * (-0.625f) - 1.0f;
    const float py = (vy - 1.6f) * (-0.625f) - 1.0f;
    const float pz = (vz - 1.6f) * (-0.625f) - 1.0f;

    const float cw[3] = {py, px, px};   // plane -> W coord
    const float ch[3] = {pz, pz, py};   // plane -> H coord

    const int Rs[3] = {128, 256, 512};
    const unsigned base_px[9] = {0u,      16384u,  32768u,
                                 49152u,  114688u, 180224u,
                                 245760u, 507904u, 770048u};

    const uint4* __restrict__ gp = (const uint4*)g_tp;  // 4 uint4 per pixel
    // lane q writes channels [8q, 8q+8) of each plane-block of 32
    float4* outp = (float4*)(out + (size_t)pt * 288) + 2 * q;

    #pragma unroll
    for (int l = 0; l < 3; l++) {
        const int   R   = Rs[l];
        const float Rm1 = (float)(R - 1);
        #pragma unroll
        for (int p = 0; p < 3; p++) {
            float x = (cw[p] + 1.0f) * 0.5f * Rm1;
            x = fminf(fmaxf(x, 0.0f), Rm1);
            float y = (ch[p] + 1.0f) * 0.5f * Rm1;
            y = fminf(fmaxf(y, 0.0f), Rm1);

            const float x0f = floorf(x), y0f = floorf(y);
            const float wx = x - x0f,    wy = y - y0f;
            const int x0 = (int)x0f,     y0 = (int)y0f;
            const int x1 = min(x0 + 1, R - 1);
            const int y1 = min(y0 + 1, R - 1);

            const uint4* base = gp + ((size_t)base_px[l * 3 + p] << 2) + q;
            const uint4 u00 = __ldg(base + ((size_t)(y0 * R + x0) << 2));
            const uint4 u01 = __ldg(base + ((size_t)(y0 * R + x1) << 2));
            const uint4 u10 = __ldg(base + ((size_t)(y1 * R + x0) << 2));
            const uint4 u11 = __ldg(base + ((size_t)(y1 * R + x1) << 2));

            float4 r0, r1;
            lerp8(u00, u01, u10, u11, wx, wy, r0, r1);

            outp[(l * 3 + p) * 8 + 0] = r0;   // 32 floats/plane: lane q ->
            outp[(l * 3 + p) * 8 + 1] = r1;   // float4 slots 2q, 2q+1
        }
    }
}

extern "C" void kernel_launch(void* const* d_in, const int* in_sizes, int n_in,
                              void* d_out, int out_size) {
    const float* pts = (const float*)d_in[0];
    const int n = in_sizes[0] / 3;  // 300000 points

    GridPtrs ptrs;
    for (int i = 0; i < 9; i++) ptrs.g[i] = (const float*)d_in[1 + i];

    transpose_all<<<TOTAL_TILES, 256>>>(ptrs);

    // 8 points per warp, 8 warps per block -> 64 points per block
    const int blocks = (n + 63) / 64;
    sample_kernel<<<blocks, 256>>>(pts, (float*)d_out, n);
}

// round 5
// speedup vs baseline: 1.9855x; 1.1146x over previous
#include <cuda_runtime.h>
#include <cuda_fp16.h>

// ---------------------------------------------------------------------------
// Tri-plane sampling, channel-last fp16 scratch:
//   phase 1: fused transpose of 9 grids [32,R,R] -> [R*R,32] fp16 (66 MB,
//            L2-resident), HBM-roofline streaming. Unchanged from R4.
//   phase 2: 4 points/warp, 8 lanes/point. One LDG.128 per ROW fetches both
//            x-corners (contiguous 128B); y-lerp local, x-lerp via one
//            shfl_xor round; one STG.128 covers the 128B output line.
//            L1 line-touches/pt: 27 load + 9 store (vs 36+18 in R4).
// ---------------------------------------------------------------------------

#define TOTAL_PX 1032192u   // 3*128^2 + 3*256^2 + 3*512^2
__device__ __half g_tp[TOTAL_PX * 32 + 64];  // 66 MB + 1-pixel pad for row overread

__constant__ unsigned c_base_px[9] = {0u,      16384u,  32768u,
                                      49152u,  114688u, 180224u,
                                      245760u, 507904u, 770048u};
__constant__ int      c_npix[9]    = {16384, 16384, 16384,
                                      65536, 65536, 65536,
                                      262144, 262144, 262144};
__constant__ int      c_tile_start[9] = {0, 128, 256,
                                         384, 896, 1408,
                                         1920, 3968, 6016};
#define TOTAL_TILES 8064    // TOTAL_PX / 128

struct GridPtrs { const float* g[9]; };

__global__ void __launch_bounds__(256)
transpose_all(GridPtrs ptrs) {
    __shared__ float tile[128][33];   // stride 33: conflict-free both phases
    const int b = blockIdx.x;

    int gi = 0;
    #pragma unroll
    for (int i = 1; i < 9; i++)
        if (b >= c_tile_start[i]) gi = i;

    const float* __restrict__ g = ptrs.g[gi];
    const int npix = c_npix[gi];
    const int pix0 = (b - c_tile_start[gi]) * 128;

    const int tx = threadIdx.x & 31;
    const int ty = threadIdx.x >> 5;   // warp id 0..7

    #pragma unroll
    for (int c = ty; c < 32; c += 8) {
        const float* row = g + (size_t)c * npix + pix0;
        #pragma unroll
        for (int j = 0; j < 4; j++)
            tile[32 * j + tx][c] = __ldg(row + 32 * j + tx);
    }
    __syncthreads();

    __half2* dst = (__half2*)g_tp + ((size_t)c_base_px[gi] + pix0) * 16;
    const int hl = tx & 15;
    #pragma unroll
    for (int s = 0; s < 8; s++) {
        const int pix = ty * 16 + s * 2 + (tx >> 4);
        const float a  = tile[pix][2 * hl];
        const float c2 = tile[pix][2 * hl + 1];
        dst[(size_t)pix * 16 + hl] = __floats2half2_rn(a, c2);
    }
}

__global__ void __launch_bounds__(256)
sample_kernel(const float* __restrict__ pts, float* __restrict__ out, int n) {
    const int warp = (int)((blockIdx.x * 256u + threadIdx.x) >> 5);
    const int lane = threadIdx.x & 31;
    const int s    = lane & 7;            // sub-lane within point: 16B chunk of 128B row-pair
    const int pt   = warp * 4 + (lane >> 3);
    const int ptc  = min(pt, n - 1);      // clamp so shuffles stay full-warp
    const bool live = (pt < n);

    const float vx = __ldg(pts + 3 * (size_t)ptc + 0);
    const float vy = __ldg(pts + 3 * (size_t)ptc + 1);
    const float vz = __ldg(pts + 3 * (size_t)ptc + 2);

    // p = (v - 1.6) * (-0.625) - 1
    const float px = (vx - 1.6f) * (-0.625f) - 1.0f;
    const float py = (vy - 1.6f) * (-0.625f) - 1.0f;
    const float pz = (vz - 1.6f) * (-0.625f) - 1.0f;

    const float cw[3] = {py, px, px};   // plane -> W coord
    const float ch[3] = {pz, pz, py};   // plane -> H coord

    const int Rs[3] = {128, 256, 512};
    const unsigned base_px[9] = {0u,      16384u,  32768u,
                                 49152u,  114688u, 180224u,
                                 245760u, 507904u, 770048u};

    const uint4* __restrict__ gp = (const uint4*)g_tp;  // 4 uint4 per pixel
    const int  g4  = s & 3;        // channel group: channels [8*g4, 8*g4+8)
    const int  h   = s >> 2;       // which float4 half of the group this lane stores
    const bool isR = (s >= 4);     // lane holds the x1 (right) corner after load

    float* outp = out + (size_t)ptc * 288;

    #pragma unroll
    for (int l = 0; l < 3; l++) {
        const int   R   = Rs[l];
        const float Rm1 = (float)(R - 1);
        #pragma unroll
        for (int p = 0; p < 3; p++) {
            float x = (cw[p] + 1.0f) * 0.5f * Rm1;
            x = fminf(fmaxf(x, 0.0f), Rm1);
            float y = (ch[p] + 1.0f) * 0.5f * Rm1;
            y = fminf(fmaxf(y, 0.0f), Rm1);

            const float x0f = floorf(x), y0f = floorf(y);
            const float wx = x - x0f,    wy = y - y0f;
            const int x0 = (int)x0f,     y0 = (int)y0f;
            const int y1 = min(y0 + 1, R - 1);
            // NOTE: x1 is implicit — the 128B row-pair load covers pixels
            // x0 and x0+1. When x0 == R-1, wx == 0 so the overread (padded,
            // in-bounds, finite) contributes nothing.

            const uint4* base = gp + ((size_t)base_px[l * 3 + p] << 2) + s;
            const uint4 a = __ldg(base + ((size_t)(y0 * R + x0) << 2));  // row y0: x0|x1
            const uint4 b = __ldg(base + ((size_t)(y1 * R + x0) << 2));  // row y1: x0|x1

            // y-lerp locally in fp32: 8 channels of this lane's x-corner
            const float iwy = 1.0f - wy;
            float ry[8];
            #pragma unroll
            for (int k = 0; k < 4; k++) {
                const unsigned ua = (&a.x)[k], ub = (&b.x)[k];
                const float2 fa = __half22float2(*(const __half2*)&ua);
                const float2 fb = __half22float2(*(const __half2*)&ub);
                ry[2 * k + 0] = fa.x * iwy + fb.x * wy;
                ry[2 * k + 1] = fa.y * iwy + fb.y * wy;
            }

            // x-lerp via shuffle with the partner corner (lane ^ 4)
            const float iwx = 1.0f - wx;
            float r[8];
            #pragma unroll
            for (int k = 0; k < 8; k++) {
                const float o = __shfl_xor_sync(0xffffffffu, ry[k], 4);
                r[k] = isR ? (o * iwx + ry[k] * wx)
                           : (ry[k] * iwx + o * wx);
            }

            // one STG.128 per point-plane: 8 lanes cover the 128B line
            if (live) {
                float4 v;
                v.x = r[4 * h + 0]; v.y = r[4 * h + 1];
                v.z = r[4 * h + 2]; v.w = r[4 * h + 3];
                *(float4*)(outp + (l * 3 + p) * 32 + 8 * g4 + 4 * h) = v;
            }
        }
    }
}

extern "C" void kernel_launch(void* const* d_in, const int* in_sizes, int n_in,
                              void* d_out, int out_size) {
    const float* pts = (const float*)d_in[0];
    const int n = in_sizes[0] / 3;  // 300000 points

    GridPtrs ptrs;
    for (int i = 0; i < 9; i++) ptrs.g[i] = (const float*)d_in[1 + i];

    transpose_all<<<TOTAL_TILES, 256>>>(ptrs);

    // 4 points per warp, 8 warps per block -> 32 points per block
    const int blocks = (n + 31) / 32;
    sample_kernel<<<blocks, 256>>>(pts, (float*)d_out, n);
}